// round 16
// baseline (speedup 1.0000x reference)
#include <cuda_runtime.h>
#include <cuda_fp16.h>
#include <math.h>
#include <stdint.h>

#define HH 28
#define WW 28
#define P 784
#define NB 32768
#define NBB 64                      // batches per block
#define NBLK (NB / NBB)             // 512
#define THREADS 256
#define PITCH_B 136                 // bytes per image row in smem (68 halves)
#define IMG_BYTES (P * PITCH_B)     // 106624 -> 2 CTAs/SM
#define REC_U32 64                  // per-pixel table record: 256B

// Per-pixel table: u32[64] record. [0..25] = f32 weights (tap 25 = 0 pad),
// [28..53] = u32 byte row-offsets (q * 136), rest pad.
__device__ __align__(16) uint32_t g_tab[P * REC_U32];

__global__ void tab_kernel(const float* __restrict__ pos2d,
                           const float* __restrict__ weight) {
    int p = threadIdx.x;
    if (p >= P) return;
    float px = pos2d[2 * p + 0];
    float py = pos2d[2 * p + 1];
    float sw = fmaxf(weight[p], 0.0f);
    float ce0 = rintf(px);   // round-half-to-even == jnp.round
    float ce1 = rintf(py);

    uint32_t* rec = g_tab + p * REC_U32;
    int k = 0;
    #pragma unroll
    for (int i0 = -2; i0 <= 2; i0++) {
        #pragma unroll
        for (int i1 = -2; i1 <= 2; i1++, k++) {
            float cr0 = ce0 + (float)i0;
            float cr1 = ce1 + (float)i1;
            int c0 = (int)cr0;
            int c1 = (int)cr1;
            bool inb = (c0 >= 0) && (c0 < HH) && (c1 >= 0) && (c1 < WW);
            int id0 = min(max(c0, 0), HH - 1);
            int id1 = min(max(c1, 0), WW - 1);
            float d0 = cr0 - px;
            float d1 = cr1 - py;
            float wv = expf(-0.5f * (d0 * d0 + d1 * d1)) * sw;
            if (!inb) wv = 0.0f;
            rec[k] = __float_as_uint(wv);
            rec[28 + k] = (uint32_t)((id0 * WW + id1) * PITCH_B);
        }
    }
    rec[25] = 0u;        // dummy tap 25: weight 0
    rec[28 + 25] = 0u;   // offset 0 (safe in-bounds read)
}

__global__ __launch_bounds__(THREADS, 2) void gather2(const float* __restrict__ x,
                                                      float* __restrict__ out) {
    extern __shared__ __align__(16) char dsm[];
    const int tid = threadIdx.x;
    const int wid = tid >> 5;
    const int lane = tid & 31;
    const int B0 = blockIdx.x * NBB;

    // ---- Load phase: x[b][p] f32 -> smem img[p][batch-half2] fp16 ----
    // For batch pair m (0..31): two coalesced LDG rows, pack half2, store at
    // img[p]*136 + m*4. Store stride 136B between lanes = 34 words -> 2-way
    // conflict only. fp16 rounding subsumes the |x|<=1e-8 clamp.
    for (int g = wid; g < 1024; g += 8) {
        const int m = g >> 5;     // batch pair
        const int s = g & 31;     // pixel strip
        if (s < 25) {
            const int px = s * 32 + lane;
            if (px < P) {
                float v0 = x[(size_t)(B0 + 2 * m) * P + px];
                float v1 = x[(size_t)(B0 + 2 * m + 1) * P + px];
                __half2 h = __floats2half2_rn(v0, v1);
                *(__half2*)(dsm + px * PITCH_B + m * 4) = h;
            }
        }
    }
    __syncthreads();

    // ---- Compute: warp-uniform row reads, lane <-> 2 batches ----
    const char* lane_ptr = dsm + lane * 4;
    const char* tabc = (const char*)g_tab;

    for (int c = wid; c < 49; c += 8) {
        const int px0 = c * 16;
        float big[32];
        #pragma unroll
        for (int i = 0; i < 32; i++) big[i] = 0.0f;

        #pragma unroll 2
        for (int i = 0; i < 16; i++) {
            const char* rec = tabc + (size_t)(px0 + i) * 256;
            float ax = 0.0f;
            float ay = 0.0f;
            #pragma unroll
            for (int g = 0; g < 13; g++) {
                float2 w2 = __ldg((const float2*)(rec + 8 * g));
                uint2 o2 = __ldg((const uint2*)(rec + 112 + 8 * g));
                __half2 h0 = *(const __half2*)(lane_ptr + o2.x);
                float2 f0 = __half22float2(h0);
                ax = fmaf(f0.x, w2.x, ax);
                ay = fmaf(f0.y, w2.x, ay);
                __half2 h1 = *(const __half2*)(lane_ptr + o2.y);
                float2 f1 = __half22float2(h1);
                ax = fmaf(f1.x, w2.y, ax);
                ay = fmaf(f1.y, w2.y, ay);
            }
            big[i] = ax;        // (pixel px0+i, batch B0+2*lane)
            big[16 + i] = ay;   // (pixel px0+i, batch B0+2*lane+1)
        }

        // ---- 32x32 XOR register transpose ----
        // Pre:  big[i][lane] = (px0 + (i&15), B0 + 2*lane + (i>>4))
        // Post: big[i][lane] = (px0 + (lane&15), B0 + 2*i + (lane>>4))
        #pragma unroll
        for (int m = 16; m >= 1; m >>= 1) {
            #pragma unroll
            for (int i = 0; i < 32; i++) {
                if ((i & m) == 0) {
                    float send = (lane & m) ? big[i] : big[i | m];
                    float recv = __shfl_xor_sync(0xffffffffu, send, m);
                    if (lane & m) big[i] = recv;
                    else big[i | m] = recv;
                }
            }
        }

        // ---- Coalesced stores: 2 x 64B segments per STG ----
        const int pxs = px0 + (lane & 15);
        const int bofs = B0 + (lane >> 4);
        #pragma unroll
        for (int i = 0; i < 32; i++) {
            out[(size_t)(bofs + 2 * i) * P + pxs] = big[i];
        }
    }
}

extern "C" void kernel_launch(void* const* d_in, const int* in_sizes, int n_in,
                              void* d_out, int out_size) {
    const float* x      = (const float*)d_in[0];  // (32768,1,28,28) f32
    const float* pos2d  = (const float*)d_in[1];  // (28,28,2) f32
    const float* weight = (const float*)d_in[2];  // (28,28) f32
    float* out = (float*)d_out;

    cudaFuncSetAttribute(gather2, cudaFuncAttributeMaxDynamicSharedMemorySize, IMG_BYTES);

    tab_kernel<<<1, P>>>(pos2d, weight);
    gather2<<<NBLK, THREADS, IMG_BYTES>>>(x, out);
}